// round 17
// baseline (speedup 1.0000x reference)
#include <cuda_runtime.h>
#include <cuda_fp16.h>
#include <cstdint>

#define N_NODES 50000
#define FIN 512
#define FOUT 128
#define MAXE 1000000

#define SCHUNK 512
#define NCHUNK ((N_NODES + SCHUNK - 1) / SCHUNK)   // 98

// Static device scratch (no allocation anywhere):
__device__ __half g_pre[(size_t)N_NODES * FOUT];         // fp16 pre_sup, 12.8 MB
__device__ int   g_counts[2][N_NODES];
__device__ int   g_rowstart[2][N_NODES + 1];
__device__ int   g_cursor[2][N_NODES];
__device__ int   g_chunksum[2][NCHUNK];
__device__ int   g_chunkoff[2][NCHUNK];
__device__ int2  g_edges[2][MAXE];                       // packed (col, val-bits)

// ---------------------------------------------------------------------------
// helpers
// ---------------------------------------------------------------------------
__device__ __forceinline__ uint32_t f2tf32(float f) {
    uint32_t u;
    asm("cvt.rna.tf32.f32 %0, %1;" : "=r"(u) : "f"(f));
    return u;
}

__device__ __forceinline__ void mma_tf32(float* d, const uint32_t* a, const uint32_t* b) {
    asm("mma.sync.aligned.m16n8k8.row.col.f32.tf32.tf32.f32 "
        "{%0,%1,%2,%3}, {%4,%5,%6,%7}, {%8,%9}, {%0,%1,%2,%3};"
        : "+f"(d[0]), "+f"(d[1]), "+f"(d[2]), "+f"(d[3])
        : "r"(a[0]), "r"(a[1]), "r"(a[2]), "r"(a[3]), "r"(b[0]), "r"(b[1]));
}

__device__ __forceinline__ uint32_t sptr(const void* p) {
    return (uint32_t)__cvta_generic_to_shared(p);
}

__device__ __forceinline__ void cp16(uint32_t s, const void* g, int src_sz) {
    asm volatile("cp.async.ca.shared.global [%0], [%1], 16, %2;"
                 :: "r"(s), "l"(g), "r"(src_sz));
}

// ---------------------------------------------------------------------------
// tf32 GEMM, cp.async double-buffered, N-HALF version.
// Computes g_pre[:, n_off : n_off+64] (fp16) = A[M, FIN] * B[FIN, n_off:+64].
// Block tile M=128 x N=64, K-chunk 16, 256 threads = 8 warps (4M x 2N),
// warp tile 32x32. occ 3 -> 444 concurrent CTAs >= 391 blocks: single wave.
// As[m][k] stride 20 / Bs[k][n] stride 72: frag banks bijective, conflict-free.
// ---------------------------------------------------------------------------
#define GM 128
#define GN 64
#define GK 16
#define ASTR 20
#define BSTR 72
#define NITER (FIN / GK)   // 32

__global__ __launch_bounds__(256, 3) void gemm_tf32_nhalf(const float* __restrict__ A,
                                                          const float* __restrict__ B,
                                                          int n_off) {
    __shared__ float As[2][GM][ASTR];   // 20480 B
    __shared__ float Bs[2][GK][BSTR];   // 9216 B

    const int tid = threadIdx.x;
    const int w = tid >> 5, l = tid & 31;
    const int wm = (w >> 1) * 32;          // 4 warps over M
    const int wn = (w & 1) * 32;           // 2 warps over N (of 64)
    const int g = l >> 2, tg = l & 3;
    const int block_row = blockIdx.x * GM;

    float acc[2][4][4];
#pragma unroll
    for (int mi = 0; mi < 2; mi++)
#pragma unroll
        for (int ni = 0; ni < 4; ni++)
#pragma unroll
            for (int q = 0; q < 4; q++) acc[mi][ni][q] = 0.f;

    // A loader: row am = tid>>1, k-offset (tid&1)*8, two cp16
    const int am = tid >> 1;
    const int ak = (tid & 1) * 8;
    const int arow = block_row + am;
    const int asz = (arow < N_NODES) ? 16 : 0;
    const float* aG = A + (size_t)arow * FIN + ak;
    // B loader: k-row bk = tid>>4, n-offset (tid&15)*4, one cp16 (16x64 floats)
    const int bk = tid >> 4;
    const int bn = (tid & 15) * 4;
    const float* bG = B + (size_t)bk * FOUT + n_off + bn;

    const uint32_t sA0 = sptr(&As[0][am][ak]);
    const uint32_t sA1 = sptr(&As[1][am][ak]);
    const uint32_t sB0 = sptr(&Bs[0][bk][bn]);
    const uint32_t sB1 = sptr(&Bs[1][bk][bn]);

    cp16(sA0, aG, asz);      cp16(sA0 + 16, aG + 4, asz);
    cp16(sB0, bG, 16);
    asm volatile("cp.async.commit_group;");

    for (int it = 0; it < NITER; it++) {
        const int buf = it & 1;
        if (it + 1 < NITER) {
            const float* a0 = aG + (it + 1) * GK;
            const float* b0 = bG + (size_t)(it + 1) * GK * FOUT;
            const uint32_t sa = buf ? sA0 : sA1;
            const uint32_t sb = buf ? sB0 : sB1;
            cp16(sa, a0, asz);   cp16(sa + 16, a0 + 4, asz);
            cp16(sb, b0, 16);
        }
        asm volatile("cp.async.commit_group;");
        asm volatile("cp.async.wait_group 1;");
        __syncthreads();

#pragma unroll
        for (int ks = 0; ks < 2; ks++) {
            const int kb = ks * 8;
            uint32_t afr[2][4], bfr[4][2];
#pragma unroll
            for (int mi = 0; mi < 2; mi++) {
                const int m = wm + mi * 16;
                afr[mi][0] = f2tf32(As[buf][m + g][kb + tg]);
                afr[mi][1] = f2tf32(As[buf][m + g + 8][kb + tg]);
                afr[mi][2] = f2tf32(As[buf][m + g][kb + tg + 4]);
                afr[mi][3] = f2tf32(As[buf][m + g + 8][kb + tg + 4]);
            }
#pragma unroll
            for (int ni = 0; ni < 4; ni++) {
                const int n = wn + ni * 8 + g;
                bfr[ni][0] = f2tf32(Bs[buf][kb + tg][n]);
                bfr[ni][1] = f2tf32(Bs[buf][kb + tg + 4][n]);
            }
#pragma unroll
            for (int mi = 0; mi < 2; mi++)
#pragma unroll
                for (int ni = 0; ni < 4; ni++)
                    mma_tf32(acc[mi][ni], afr[mi], bfr[ni]);
        }
        __syncthreads();
    }

    // Epilogue: fp16 store into cols [n_off, n_off+64)
#pragma unroll
    for (int mi = 0; mi < 2; mi++) {
        const int r0 = block_row + wm + mi * 16 + g;
#pragma unroll
        for (int ni = 0; ni < 4; ni++) {
            const int c = n_off + wn + ni * 8 + tg * 2;
            if (r0 < N_NODES)
                *(__half2*)(g_pre + (size_t)r0 * FOUT + c) =
                    __floats2half2_rn(acc[mi][ni][0], acc[mi][ni][1]);
            if (r0 + 8 < N_NODES)
                *(__half2*)(g_pre + (size_t)(r0 + 8) * FOUT + c) =
                    __floats2half2_rn(acc[mi][ni][2], acc[mi][ni][3]);
        }
    }
}

// ---------------------------------------------------------------------------
// CSR build (R14 version: single edge list per branch, no partitioning)
// ---------------------------------------------------------------------------
__global__ void zero_counts_kernel() {
    int i = blockIdx.x * blockDim.x + threadIdx.x;
    if (i < 2 * N_NODES) ((int*)g_counts)[i] = 0;
}

__global__ __launch_bounds__(256) void hist_kernel(const int* __restrict__ idx0,
                                                   const int* __restrict__ idx1, int E) {
    const int* idx = blockIdx.y ? idx1 : idx0;
    const int stride = gridDim.x * blockDim.x;
    int t = blockIdx.x * blockDim.x + threadIdx.x;
    int rows[4];
    bool ok[4];
#pragma unroll
    for (int r = 0; r < 4; r++) {
        int e = t + r * stride;
        ok[r] = (e < E);
        if (ok[r]) {
            rows[r] = idx[e];
            int col = idx[E + e];
            if ((unsigned)rows[r] >= N_NODES || (unsigned)col >= N_NODES) ok[r] = false;
        }
    }
#pragma unroll
    for (int r = 0; r < 4; r++)
        if (ok[r]) atomicAdd(&g_counts[blockIdx.y][rows[r]], 1);
}

__global__ __launch_bounds__(SCHUNK) void scan1_kernel() {
    const int b = blockIdx.y;
    const int t = threadIdx.x;
    const int bin = blockIdx.x * SCHUNK + t;

    int v = (bin < N_NODES) ? g_counts[b][bin] : 0;
    __shared__ int s[SCHUNK];
    s[t] = v;
    __syncthreads();
#pragma unroll
    for (int off = 1; off < SCHUNK; off <<= 1) {
        int u = (t >= off) ? s[t - off] : 0;
        __syncthreads();
        s[t] += u;
        __syncthreads();
    }
    if (bin < N_NODES) g_rowstart[b][bin] = s[t] - v;
    if (t == SCHUNK - 1) g_chunksum[b][blockIdx.x] = s[t];
}

__global__ __launch_bounds__(128) void scan2_kernel() {
    const int b = blockIdx.x;
    const int t = threadIdx.x;
    int v = (t < NCHUNK) ? g_chunksum[b][t] : 0;
    __shared__ int s[128];
    s[t] = v;
    __syncthreads();
#pragma unroll
    for (int off = 1; off < 128; off <<= 1) {
        int u = (t >= off) ? s[t - off] : 0;
        __syncthreads();
        s[t] += u;
        __syncthreads();
    }
    if (t < NCHUNK) g_chunkoff[b][t] = s[t] - v;
    if (t == NCHUNK - 1) g_rowstart[b][N_NODES] = s[t];
}

__global__ __launch_bounds__(SCHUNK) void scan3_kernel() {
    const int b = blockIdx.y;
    const int bin = blockIdx.x * SCHUNK + threadIdx.x;
    if (bin < N_NODES) {
        int r = g_rowstart[b][bin] + g_chunkoff[b][blockIdx.x];
        g_rowstart[b][bin] = r;
        g_cursor[b][bin] = r;
    }
}

__global__ __launch_bounds__(256) void scatter_kernel(const int* __restrict__ idx0,
                                                      const float* __restrict__ v0,
                                                      const int* __restrict__ idx1,
                                                      const float* __restrict__ v1, int E) {
    const int b = blockIdx.y;
    const int* idx = b ? idx1 : idx0;
    const float* vals = b ? v1 : v0;
    const int stride = gridDim.x * blockDim.x;
    int t = blockIdx.x * blockDim.x + threadIdx.x;

    int rows[4], cols[4], pos[4];
    float vv[4];
    bool ok[4];
#pragma unroll
    for (int r = 0; r < 4; r++) {
        int e = t + r * stride;
        ok[r] = (e < E);
        if (ok[r]) {
            rows[r] = idx[e];
            cols[r] = idx[E + e];
            vv[r] = vals[e];
            if ((unsigned)rows[r] >= N_NODES || (unsigned)cols[r] >= N_NODES) ok[r] = false;
        }
    }
#pragma unroll
    for (int r = 0; r < 4; r++)
        if (ok[r]) pos[r] = atomicAdd(&g_cursor[b][rows[r]], 1);
#pragma unroll
    for (int r = 0; r < 4; r++)
        if (ok[r] && pos[r] < MAXE)
            g_edges[b][pos[r]] = make_int2(cols[r], __float_as_int(vv[r]));
}

// ---------------------------------------------------------------------------
// Gather SpMM over FEATURE-half p: all edges of the row, 64 cols per pass.
// Lane l reads one uint (2 halfs) per edge; writes final bias+ReLU'd float2.
// 8-deep edge unroll for MLP (4B loads).
// ---------------------------------------------------------------------------
__global__ __launch_bounds__(256) void spmm_half_kernel(float* __restrict__ out,
                                                        const float* __restrict__ bias,
                                                        int p) {
    const int b = blockIdx.y;
    const int warp = threadIdx.x >> 5;
    const int lane = threadIdx.x & 31;
    const int row = blockIdx.x * 8 + warp;
    if (row >= N_NODES) return;

    const int beg = g_rowstart[b][row];
    const int end = g_rowstart[b][row + 1];
    const int2* __restrict__ edges = g_edges[b];
    const uint32_t* __restrict__ pre1 = (const uint32_t*)g_pre;   // 64 units/row
    const int off = p * 32 + lane;                                 // unit within row

    float2 acc = make_float2(0.f, 0.f);
    int e = beg;
    for (; e + 8 <= end; e += 8) {
        int2 ed[8];
        uint32_t m[8];
#pragma unroll
        for (int j = 0; j < 8; j++) ed[j] = edges[e + j];
#pragma unroll
        for (int j = 0; j < 8; j++) m[j] = pre1[(size_t)ed[j].x * 64 + off];
#pragma unroll
        for (int j = 0; j < 8; j++) {
            float v = __int_as_float(ed[j].y);
            float2 h = __half22float2(*(__half2*)&m[j]);
            acc.x += v * h.x;
            acc.y += v * h.y;
        }
    }
    for (; e < end; e++) {
        int2 ed = edges[e];
        float v = __int_as_float(ed.y);
        float2 h = __half22float2(*(__half2*)&pre1[(size_t)ed.x * 64 + off]);
        acc.x += v * h.x;
        acc.y += v * h.y;
    }

    float2 bb = ((const float2*)bias)[off];
    acc.x = fmaxf(acc.x + bb.x, 0.f);
    acc.y = fmaxf(acc.y + bb.y, 0.f);

    float2* orow = (float2*)(out + ((size_t)b * N_NODES + row) * FOUT + p * 64);
    orow[lane] = acc;
}

// ---------------------------------------------------------------------------
// Launch: [s2: GEMM(n=0) -> ev1 -> GEMM(n=64) -> ev2]
//         [0: build -> wait(ev1) -> spmm(p=0) -> wait(ev2) -> spmm(p=1)]
// ---------------------------------------------------------------------------
extern "C" void kernel_launch(void* const* d_in, const int* in_sizes, int n_in,
                              void* d_out, int out_size) {
    const float* x     = (const float*)d_in[0];
    const int*   sidx  = (const int*)d_in[1];
    const float* svals = (const float*)d_in[2];
    const int*   oidx  = (const int*)d_in[3];
    const float* ovals = (const float*)d_in[4];
    const float* W     = (const float*)d_in[5];
    const float* bias  = (const float*)d_in[6];
    float* out = (float*)d_out;

    int E = in_sizes[2];
    if (E > MAXE) E = MAXE;

    static cudaStream_t s2 = nullptr;
    static cudaEvent_t ev_fork = nullptr, ev_g1 = nullptr, ev_g2 = nullptr;
    if (!s2) {
        cudaStreamCreateWithFlags(&s2, cudaStreamNonBlocking);
        cudaEventCreateWithFlags(&ev_fork, cudaEventDisableTiming);
        cudaEventCreateWithFlags(&ev_g1, cudaEventDisableTiming);
        cudaEventCreateWithFlags(&ev_g2, cudaEventDisableTiming);
    }

    const int NB = (N_NODES + GM - 1) / GM;   // 391 blocks per N-half

    // Fork: N-half GEMMs on side stream
    cudaEventRecord(ev_fork, 0);
    cudaStreamWaitEvent(s2, ev_fork, 0);
    gemm_tf32_nhalf<<<NB, 256, 0, s2>>>(x, W, 0);
    cudaEventRecord(ev_g1, s2);
    gemm_tf32_nhalf<<<NB, 256, 0, s2>>>(x, W, 64);
    cudaEventRecord(ev_g2, s2);

    // CSR build on default stream (hides under GEMM half 1)
    zero_counts_kernel<<<(2 * N_NODES + 255) / 256, 256>>>();
    dim3 eg4((E + 1023) / 1024, 2);
    hist_kernel<<<eg4, 256>>>(sidx, oidx, E);
    dim3 cg(NCHUNK, 2);
    scan1_kernel<<<cg, SCHUNK>>>();
    scan2_kernel<<<2, 128>>>();
    scan3_kernel<<<cg, SCHUNK>>>();
    scatter_kernel<<<eg4, 256>>>(sidx, svals, oidx, ovals, E);

    // spmm over feature-half 0 (overlaps GEMM half 2), then half 1
    dim3 sg((N_NODES + 7) / 8, 2);
    cudaStreamWaitEvent(0, ev_g1, 0);
    spmm_half_kernel<<<sg, 256>>>(out, bias, 0);
    cudaStreamWaitEvent(0, ev_g2, 0);
    spmm_half_kernel<<<sg, 256>>>(out, bias, 1);
}